// round 14
// baseline (speedup 1.0000x reference)
#include <cuda_runtime.h>
#include <cuda_fp16.h>
#include <cstdint>

#define BATCH 4
#define SEQ   2048
#define EMB   1024
#define MTOT  (BATCH * SEQ)                 // 8192
#define NELEM ((long)MTOT * EMB)            // 8388608
#define NP    ((long)BATCH * SEQ * SEQ)     // 16777216

// ---------------------------------------------------------------------------
// Scratch — packed fp16 planes.
// ---------------------------------------------------------------------------
__device__ __half g_x1[3 * NELEM];           // [xq | xk | xv] fp16
__device__ __half g_W1[(long)EMB * EMB];
__device__ __half g_QKV[3 * NELEM];          // [Q | K | V] fp16
__device__ __half g_P1[NP];                  // un-normalized exp(s), fp16
__device__ float  g_part[(long)MTOT * 32];   // per-(row, col-tile) partial sums

// ---------------------------------------------------------------------------
__device__ __forceinline__ uint32_t smem_u32(const void* p) {
    uint32_t a;
    asm("{ .reg .u64 t; cvta.to.shared.u64 t, %1; cvt.u32.u64 %0, t; }" : "=r"(a) : "l"(p));
    return a;
}

#define LDSM4(r, addr) \
    asm volatile("ldmatrix.sync.aligned.m8n8.x4.shared.b16 {%0,%1,%2,%3}, [%4];" \
        : "=r"((r)[0]), "=r"((r)[1]), "=r"((r)[2]), "=r"((r)[3]) : "r"(addr))

#define LDSM4_T(r, addr) \
    asm volatile("ldmatrix.sync.aligned.m8n8.x4.trans.shared.b16 {%0,%1,%2,%3}, [%4];" \
        : "=r"((r)[0]), "=r"((r)[1]), "=r"((r)[2]), "=r"((r)[3]) : "r"(addr))

#define MMA_F16(d, a, b0, b1) \
    asm volatile("mma.sync.aligned.m16n8k16.row.col.f32.f16.f16.f32 " \
        "{%0,%1,%2,%3}, {%4,%5,%6,%7}, {%8,%9}, {%0,%1,%2,%3};" \
        : "+f"((d)[0]), "+f"((d)[1]), "+f"((d)[2]), "+f"((d)[3]) \
        : "r"((a)[0]), "r"((a)[1]), "r"((a)[2]), "r"((a)[3]), "r"(b0), "r"(b1))

// CTA tile 128x64, BK=64. Row pitch 144B (64 fp16 + 8 pad): odd 16B-chunk
// multiple -> conflict-free cp.async writes, LDSM reads, LDSM_T k-row reads.
// A tile: 128 x 144 = 18432. B tile: 64 x 144 = 9216. Stage = 27648.
#define A_BYTES   18432u
#define STAGE_B   27648u
#define SMEM_REQ  (2 * STAGE_B + 512)        // +512: invS staging in PV

// ---------------------------------------------------------------------------
// fp16 TC GEMM (fp32 accum): 128x64 tile, 4 warps (2m x 2n), 4 CTAs/SM.
// EXP: QK mode — epilogue does exp + causal mask + fp16 store + row partials.
// RSCALE: PV mode — prologue reduces part[] -> invS smem; epilogue row-scales.
// TRB: B stored [K][N] row-major (V direct); fragments via ldmatrix.trans.
// ---------------------------------------------------------------------------
template <bool CAUSAL, bool TRUNCK, bool BIAS, bool WF32, bool RSCALE, bool EXP, bool TRB>
__global__ void __launch_bounds__(128, 4)
gemm_f16(const __half* __restrict__ A, long strideAz,
         const __half* __restrict__ B, long strideBz, int ldb,
         int K, float alpha, const float* __restrict__ bias,
         const float* __restrict__ part,
         float* __restrict__ Cf, __half* __restrict__ Ch,
         int ldc, long strideCz)
{
    const int bx = blockIdx.x, bz = blockIdx.z;
    const int by = TRUNCK ? (gridDim.y - 1 - blockIdx.y) : blockIdx.y;
    if (CAUSAL && bx > 2 * by + 1) return;

    extern __shared__ char smem[];
    const uint32_t sbase = smem_u32(smem);

    const __half* Ab = A + (long)bz * strideAz;
    const __half* Bb = B + (long)bz * strideBz;

    const int tid = threadIdx.x, wid = tid >> 5, l = tid & 31;
    const int wr = wid >> 1, wc = wid & 1;
    const int kEnd = TRUNCK ? min(K, (by + 1) * 128) : K;
    const int nst = kEnd >> 6;                // BK=64 stages (>= 2 always)
    const int rowA0 = by * 128, rowB0 = bx * 64;

    float acc[4][4][4];
#pragma unroll
    for (int m = 0; m < 4; m++)
#pragma unroll
        for (int n = 0; n < 4; n++)
#pragma unroll
            for (int j = 0; j < 4; j++) acc[m][n][j] = 0.f;

    // 1536 x 16B chunks per stage: A 1024 (128 rows x 8 segs), B 512
#define LOAD_STAGE(sidx, buf) do { \
        const int k0_ = (sidx) * 64; \
        const uint32_t st_ = sbase + (buf) * STAGE_B; \
        _Pragma("unroll") \
        for (int i_ = 0; i_ < 12; i_++) { \
            int c_ = i_ * 128 + tid; \
            uint32_t dst_; const void* src_; \
            if (c_ < 1024) { \
                int row_ = c_ >> 3, seg_ = c_ & 7; \
                dst_ = st_ + row_ * 144 + seg_ * 16; \
                src_ = Ab + (long)(rowA0 + row_) * K + k0_ + seg_ * 8; \
            } else if (TRB) { \
                int w_ = c_ - 1024; \
                int row_ = w_ >> 3, seg_ = w_ & 7; \
                dst_ = st_ + A_BYTES + row_ * 144 + seg_ * 16; \
                src_ = Bb + (long)(k0_ + row_) * ldb + rowB0 + seg_ * 8; \
            } else { \
                int w_ = c_ - 1024; \
                int row_ = w_ >> 3, seg_ = w_ & 7; \
                dst_ = st_ + A_BYTES + row_ * 144 + seg_ * 16; \
                src_ = Bb + (long)(rowB0 + row_) * ldb + k0_ + seg_ * 8; \
            } \
            asm volatile("cp.async.cg.shared.global [%0], [%1], 16;" :: "r"(dst_), "l"(src_)); \
        } \
        asm volatile("cp.async.commit_group;"); \
    } while (0)

    LOAD_STAGE(0, 0);

    // PV prologue: reduce this CTA's 128 row-sums into smem (overlaps stage-0
    // cp.async). Same shfl-xor order as the old reduce kernel -> bit-identical.
    float* invS_s = reinterpret_cast<float*>(smem + 2 * STAGE_B);
    if (RSCALE) {
#pragma unroll 4
        for (int rr = wid * 32; rr < wid * 32 + 32; rr++) {
            const int grow = by * 128 + rr;            // row within seq
            const int ntile = (grow >> 6) + 1;
            float s = (l < ntile) ? part[((long)bz * SEQ + grow) * 32 + l] : 0.f;
#pragma unroll
            for (int o = 16; o > 0; o >>= 1) s += __shfl_xor_sync(0xffffffffu, s, o);
            if (l == 0) invS_s[rr] = 1.f / s;
        }
    }

    const int lr = l & 15, lh = l >> 4;

    for (int s = 0; s < nst; s++) {
        const int b = s & 1;
        asm volatile("cp.async.wait_group 0;");
        __syncthreads();
        if (s + 1 < nst) LOAD_STAGE(s + 1, b ^ 1);

        const uint32_t st = sbase + b * STAGE_B;
#pragma unroll
        for (int kk = 0; kk < 64; kk += 16) {
            uint32_t AH[4][4], BH[2][4];
            const uint32_t kb = (kk + lh * 8) * 2;
#pragma unroll
            for (int mt = 0; mt < 4; mt++) {
                uint32_t a0 = st + (wr * 64 + mt * 16 + lr) * 144 + kb;
                LDSM4(AH[mt], a0);
            }
            if (TRB) {
#pragma unroll
                for (int np = 0; np < 2; np++) {
                    uint32_t b0 = st + A_BYTES + (kk + lr) * 144
                                + (wc * 32 + np * 16 + lh * 8) * 2;
                    LDSM4_T(BH[np], b0);
                }
#pragma unroll
                for (int mt = 0; mt < 4; mt++)
#pragma unroll
                    for (int np = 0; np < 2; np++) {
                        MMA_F16(acc[mt][2 * np],     AH[mt], BH[np][0], BH[np][1]);
                        MMA_F16(acc[mt][2 * np + 1], AH[mt], BH[np][2], BH[np][3]);
                    }
            } else {
#pragma unroll
                for (int np = 0; np < 2; np++) {
                    uint32_t b0 = st + A_BYTES + (wc * 32 + np * 16 + lr) * 144 + kb;
                    LDSM4(BH[np], b0);
                }
#pragma unroll
                for (int mt = 0; mt < 4; mt++)
#pragma unroll
                    for (int np = 0; np < 2; np++) {
                        MMA_F16(acc[mt][2 * np],     AH[mt], BH[np][0], BH[np][2]);
                        MMA_F16(acc[mt][2 * np + 1], AH[mt], BH[np][1], BH[np][3]);
                    }
            }
        }
    }
#undef LOAD_STAGE

    const int rql = l >> 2, cpl = (l & 3) * 2;

    if (EXP) {
        // ---- QK epilogue: exp + causal mask + fp16 store + row partials ----
        __syncthreads();
        float* partS = reinterpret_cast<float*>(smem);   // [2][128]
#pragma unroll
        for (int mt = 0; mt < 4; mt++) {
            const int rl = wr * 64 + mt * 16 + rql;
            const int grow = by * 128 + rl;
            float p0 = 0.f, p1 = 0.f;
#pragma unroll
            for (int nt = 0; nt < 4; nt++) {
                const int col = bx * 64 + wc * 32 + nt * 8 + cpl;
                float e0 = (col     <= grow)     ? __expf(acc[mt][nt][0] * alpha) : 0.f;
                float e1 = (col + 1 <= grow)     ? __expf(acc[mt][nt][1] * alpha) : 0.f;
                float e2 = (col     <= grow + 8) ? __expf(acc[mt][nt][2] * alpha) : 0.f;
                float e3 = (col + 1 <= grow + 8) ? __expf(acc[mt][nt][3] * alpha) : 0.f;
                __half h0 = __float2half(e0), h1 = __float2half(e1);
                __half h2 = __float2half(e2), h3 = __float2half(e3);
                const long o0 = (long)bz * strideCz + (long)grow * ldc + col;
                *reinterpret_cast<uint32_t*>(Ch + o0) =
                    (uint32_t)__half_as_ushort(h0) | ((uint32_t)__half_as_ushort(h1) << 16);
                *reinterpret_cast<uint32_t*>(Ch + o0 + 8L * ldc) =
                    (uint32_t)__half_as_ushort(h2) | ((uint32_t)__half_as_ushort(h3) << 16);
                p0 += e0 + e1;
                p1 += e2 + e3;
            }
            p0 += __shfl_xor_sync(0xffffffffu, p0, 1);
            p0 += __shfl_xor_sync(0xffffffffu, p0, 2);
            p1 += __shfl_xor_sync(0xffffffffu, p1, 1);
            p1 += __shfl_xor_sync(0xffffffffu, p1, 2);
            if ((l & 3) == 0) {
                partS[wc * 128 + rl] = p0;
                partS[wc * 128 + rl + 8] = p1;
            }
        }
        __syncthreads();
        if (tid < 128) {
            float sv = partS[tid] + partS[128 + tid];
            const_cast<float*>(part)[((long)bz * SEQ + by * 128 + tid) * 32 + bx] = sv;
        }
        return;
    }

    // ---- standard epilogue ----
#pragma unroll
    for (int mt = 0; mt < 4; mt++) {
        const int rl = wr * 64 + mt * 16 + rql;
        const long row = (long)by * 128 + rl;
        float s0 = 1.f, s1 = 1.f;
        if (RSCALE) {
            s0 = invS_s[rl];
            s1 = invS_s[rl + 8];
        }
#pragma unroll
        for (int nt = 0; nt < 4; nt++) {
            const int col = bx * 64 + wc * 32 + nt * 8 + cpl;
            float v0 = acc[mt][nt][0] * alpha, v1 = acc[mt][nt][1] * alpha;
            float v2 = acc[mt][nt][2] * alpha, v3 = acc[mt][nt][3] * alpha;
            if (RSCALE) { v0 *= s0; v1 *= s0; v2 *= s1; v3 *= s1; }
            if (BIAS) {
                float b0 = bias[col], b1 = bias[col + 1];
                v0 += b0; v1 += b1; v2 += b0; v3 += b1;
            }
            const long o0 = (long)bz * strideCz + row * ldc + col;
            const long o1 = o0 + 8L * ldc;
            if (WF32) {
                *reinterpret_cast<float2*>(Cf + o0) = make_float2(v0, v1);
                *reinterpret_cast<float2*>(Cf + o1) = make_float2(v2, v3);
            } else {
                __half h0 = __float2half(v0), h1 = __float2half(v1);
                __half h2 = __float2half(v2), h3 = __float2half(v3);
                *reinterpret_cast<uint32_t*>(Ch + o0) =
                    (uint32_t)__half_as_ushort(h0) | ((uint32_t)__half_as_ushort(h1) << 16);
                *reinterpret_cast<uint32_t*>(Ch + o1) =
                    (uint32_t)__half_as_ushort(h2) | ((uint32_t)__half_as_ushort(h3) << 16);
            }
        }
    }
}

// ---------------------------------------------------------------------------
// fp32 -> fp16, 8 elems/thread (2x float4 in, 1x uint4 out).
// y-dim: 0..2 = xq/xk/xv (n elems), 3 = W (nW elems)
// ---------------------------------------------------------------------------
__global__ void __launch_bounds__(256) cvtH4(const float* __restrict__ i0,
                                             const float* __restrict__ i1,
                                             const float* __restrict__ i2,
                                             const float* __restrict__ i3,
                                             __half* __restrict__ o0,
                                             __half* __restrict__ o1,
                                             __half* __restrict__ o2,
                                             __half* __restrict__ o3,
                                             long n, long nW)
{
    const int y = blockIdx.y;
    const float* in = (y == 0) ? i0 : (y == 1) ? i1 : (y == 2) ? i2 : i3;
    __half* out = (y == 0) ? o0 : (y == 1) ? o1 : (y == 2) ? o2 : o3;
    const long lim = (y == 3) ? nW : n;
    long i = ((long)blockIdx.x * 256 + threadIdx.x) * 8;
    if (i >= lim) return;
    float4 a = *reinterpret_cast<const float4*>(in + i);
    float4 b = *reinterpret_cast<const float4*>(in + i + 4);
    __half h0 = __float2half(a.x), h1 = __float2half(a.y);
    __half h2 = __float2half(a.z), h3 = __float2half(a.w);
    __half h4 = __float2half(b.x), h5 = __float2half(b.y);
    __half h6 = __float2half(b.z), h7 = __float2half(b.w);
    uint4 v;
    v.x = (uint32_t)__half_as_ushort(h0) | ((uint32_t)__half_as_ushort(h1) << 16);
    v.y = (uint32_t)__half_as_ushort(h2) | ((uint32_t)__half_as_ushort(h3) << 16);
    v.z = (uint32_t)__half_as_ushort(h4) | ((uint32_t)__half_as_ushort(h5) << 16);
    v.w = (uint32_t)__half_as_ushort(h6) | ((uint32_t)__half_as_ushort(h7) << 16);
    *reinterpret_cast<uint4*>(out + i) = v;
}

// ---------------------------------------------------------------------------
extern "C" void kernel_launch(void* const* d_in, const int* in_sizes, int n_in,
                              void* d_out, int out_size)
{
    (void)in_sizes; (void)n_in; (void)out_size;
    const float* xq = (const float*)d_in[0];
    const float* xk = (const float*)d_in[1];
    const float* xv = (const float*)d_in[2];
    const float* Wq = (const float*)d_in[3];
    const float* bq = (const float*)d_in[4];
    float* out = (float*)d_out;

    void *x1, *W1, *QKV, *P1, *part;
    cudaGetSymbolAddress(&x1, g_x1);
    cudaGetSymbolAddress(&W1, g_W1);
    cudaGetSymbolAddress(&QKV, g_QKV);
    cudaGetSymbolAddress(&P1, g_P1);
    cudaGetSymbolAddress(&part, g_part);

    __half* X = (__half*)x1;
    __half* Q1 = (__half*)QKV;
    __half* K1 = Q1 + NELEM;
    __half* V1 = Q1 + 2 * NELEM;

    auto kProj = gemm_f16<false, false, true, false, false, false, false>;
    auto kQK   = gemm_f16<true,  false, false, false, false, true,  false>;
    auto kPV   = gemm_f16<false, true,  false, true,  true,  false, true>;
    cudaFuncSetAttribute(kProj, cudaFuncAttributeMaxDynamicSharedMemorySize, SMEM_REQ);
    cudaFuncSetAttribute(kQK,   cudaFuncAttributeMaxDynamicSharedMemorySize, SMEM_REQ);
    cudaFuncSetAttribute(kPV,   cudaFuncAttributeMaxDynamicSharedMemorySize, SMEM_REQ);

    // 1) fp32 -> fp16 conversions (x planes + W, one launch, 8 elems/thread)
    cvtH4<<<dim3((unsigned)(NELEM / 8 / 256), 4), 256>>>(
        xq, xk, xv, Wq, X, X + NELEM, X + 2 * NELEM, (__half*)W1,
        NELEM, (long)EMB * EMB);

    // 2) one launch: Q/K/V = x @ W^T + b -> fp16
    {
        dim3 g(EMB / 64, MTOT / 128, 3);
        kProj<<<g, 128, SMEM_REQ>>>(X, NELEM, (const __half*)W1, 0, EMB,
                                    EMB, 1.0f, bq, nullptr,
                                    nullptr, Q1, EMB, NELEM);
    }

    // 3) QK + exp + mask + partial sums
    {
        dim3 g(SEQ / 64, SEQ / 128, BATCH);
        kQK<<<g, 128, SMEM_REQ>>>(Q1, (long)SEQ * EMB, K1, (long)SEQ * EMB, EMB,
                                  EMB, 0.03125f, nullptr, (const float*)part,
                                  nullptr, (__half*)P1, SEQ, (long)SEQ * SEQ);
    }

    // 4) out = invS * (E @ V) — invS reduced in-kernel from part[]
    {
        dim3 g(EMB / 64, SEQ / 128, BATCH);
        kPV<<<g, 128, SMEM_REQ>>>((const __half*)P1, (long)SEQ * SEQ,
                                  V1, (long)SEQ * EMB, EMB,
                                  SEQ, 1.0f, nullptr, (const float*)part,
                                  out, nullptr, EMB, (long)SEQ * EMB);
    }
}

// round 15
// speedup vs baseline: 1.0672x; 1.0672x over previous
#include <cuda_runtime.h>
#include <cuda_fp16.h>
#include <cstdint>

#define BATCH 4
#define SEQ   2048
#define EMB   1024
#define MTOT  (BATCH * SEQ)                 // 8192
#define NELEM ((long)MTOT * EMB)            // 8388608
#define NP    ((long)BATCH * SEQ * SEQ)     // 16777216

// ---------------------------------------------------------------------------
// Scratch — packed fp16 planes.
// ---------------------------------------------------------------------------
__device__ __half g_x1[3 * NELEM];           // [xq | xk | xv] fp16
__device__ __half g_W1[(long)EMB * EMB];
__device__ __half g_QKV[3 * NELEM];          // [Q | K | V] fp16
__device__ __half g_P1[NP];                  // un-normalized exp(s), fp16
__device__ float  g_part[(long)MTOT * 32];   // per-(row, col-tile) partial sums
__device__ float  g_invS[MTOT];              // per-row 1/sum

// ---------------------------------------------------------------------------
__device__ __forceinline__ uint32_t smem_u32(const void* p) {
    uint32_t a;
    asm("{ .reg .u64 t; cvta.to.shared.u64 t, %1; cvt.u32.u64 %0, t; }" : "=r"(a) : "l"(p));
    return a;
}

#define LDSM4(r, addr) \
    asm volatile("ldmatrix.sync.aligned.m8n8.x4.shared.b16 {%0,%1,%2,%3}, [%4];" \
        : "=r"((r)[0]), "=r"((r)[1]), "=r"((r)[2]), "=r"((r)[3]) : "r"(addr))

#define LDSM4_T(r, addr) \
    asm volatile("ldmatrix.sync.aligned.m8n8.x4.trans.shared.b16 {%0,%1,%2,%3}, [%4];" \
        : "=r"((r)[0]), "=r"((r)[1]), "=r"((r)[2]), "=r"((r)[3]) : "r"(addr))

#define MMA_F16(d, a, b0, b1) \
    asm volatile("mma.sync.aligned.m16n8k16.row.col.f32.f16.f16.f32 " \
        "{%0,%1,%2,%3}, {%4,%5,%6,%7}, {%8,%9}, {%0,%1,%2,%3};" \
        : "+f"((d)[0]), "+f"((d)[1]), "+f"((d)[2]), "+f"((d)[3]) \
        : "r"((a)[0]), "r"((a)[1]), "r"((a)[2]), "r"((a)[3]), "r"(b0), "r"(b1))

// CTA tile 128x64, BK=64. Row pitch 144B (64 fp16 + 8 pad): odd 16B-chunk
// multiple -> conflict-free cp.async writes, LDSM reads, LDSM_T k-row reads.
// A tile: 128 x 144 = 18432. B tile: 64 x 144 = 9216. Stage = 27648.
#define A_BYTES   18432u
#define STAGE_B   27648u
#define SMEM_REQ  (2 * STAGE_B)

// ---------------------------------------------------------------------------
// fp16 TC GEMM (fp32 accum): 128x64 tile, 4 warps (2m x 2n), 4 CTAs/SM.
// EXP: QK mode — epilogue does exp + causal mask + fp16 store + row partials.
// RSCALE: PV mode — multiply row r by invS[bz*SEQ+r].
// TRB: B stored [K][N] row-major (V direct); fragments via ldmatrix.trans.
// ---------------------------------------------------------------------------
template <bool CAUSAL, bool TRUNCK, bool BIAS, bool WF32, bool RSCALE, bool EXP, bool TRB>
__global__ void __launch_bounds__(128, 4)
gemm_f16(const __half* __restrict__ A, long strideAz,
         const __half* __restrict__ B, long strideBz, int ldb,
         int K, float alpha, const float* __restrict__ bias,
         const float* __restrict__ invS, float* __restrict__ part,
         float* __restrict__ Cf, __half* __restrict__ Ch,
         int ldc, long strideCz)
{
    const int bx = blockIdx.x, bz = blockIdx.z;
    const int by = TRUNCK ? (gridDim.y - 1 - blockIdx.y) : blockIdx.y;
    if (CAUSAL && bx > 2 * by + 1) return;

    extern __shared__ char smem[];
    const uint32_t sbase = smem_u32(smem);

    const __half* Ab = A + (long)bz * strideAz;
    const __half* Bb = B + (long)bz * strideBz;

    const int tid = threadIdx.x, wid = tid >> 5, l = tid & 31;
    const int wr = wid >> 1, wc = wid & 1;
    const int kEnd = TRUNCK ? min(K, (by + 1) * 128) : K;
    const int nst = kEnd >> 6;                // BK=64 stages (>= 2 always)
    const int rowA0 = by * 128, rowB0 = bx * 64;

    float acc[4][4][4];
#pragma unroll
    for (int m = 0; m < 4; m++)
#pragma unroll
        for (int n = 0; n < 4; n++)
#pragma unroll
            for (int j = 0; j < 4; j++) acc[m][n][j] = 0.f;

    // 1536 x 16B chunks per stage: A 1024 (128 rows x 8 segs), B 512
#define LOAD_STAGE(sidx, buf) do { \
        const int k0_ = (sidx) * 64; \
        const uint32_t st_ = sbase + (buf) * STAGE_B; \
        _Pragma("unroll") \
        for (int i_ = 0; i_ < 12; i_++) { \
            int c_ = i_ * 128 + tid; \
            uint32_t dst_; const void* src_; \
            if (c_ < 1024) { \
                int row_ = c_ >> 3, seg_ = c_ & 7; \
                dst_ = st_ + row_ * 144 + seg_ * 16; \
                src_ = Ab + (long)(rowA0 + row_) * K + k0_ + seg_ * 8; \
            } else if (TRB) { \
                int w_ = c_ - 1024; \
                int row_ = w_ >> 3, seg_ = w_ & 7; \
                dst_ = st_ + A_BYTES + row_ * 144 + seg_ * 16; \
                src_ = Bb + (long)(k0_ + row_) * ldb + rowB0 + seg_ * 8; \
            } else { \
                int w_ = c_ - 1024; \
                int row_ = w_ >> 3, seg_ = w_ & 7; \
                dst_ = st_ + A_BYTES + row_ * 144 + seg_ * 16; \
                src_ = Bb + (long)(rowB0 + row_) * ldb + k0_ + seg_ * 8; \
            } \
            asm volatile("cp.async.cg.shared.global [%0], [%1], 16;" :: "r"(dst_), "l"(src_)); \
        } \
        asm volatile("cp.async.commit_group;"); \
    } while (0)

    LOAD_STAGE(0, 0);

    const int lr = l & 15, lh = l >> 4;

    for (int s = 0; s < nst; s++) {
        const int b = s & 1;
        asm volatile("cp.async.wait_group 0;");
        __syncthreads();
        if (s + 1 < nst) LOAD_STAGE(s + 1, b ^ 1);

        const uint32_t st = sbase + b * STAGE_B;
#pragma unroll
        for (int kk = 0; kk < 64; kk += 16) {
            uint32_t AH[4][4], BH[2][4];
            const uint32_t kb = (kk + lh * 8) * 2;
#pragma unroll
            for (int mt = 0; mt < 4; mt++) {
                uint32_t a0 = st + (wr * 64 + mt * 16 + lr) * 144 + kb;
                LDSM4(AH[mt], a0);
            }
            if (TRB) {
#pragma unroll
                for (int np = 0; np < 2; np++) {
                    uint32_t b0 = st + A_BYTES + (kk + lr) * 144
                                + (wc * 32 + np * 16 + lh * 8) * 2;
                    LDSM4_T(BH[np], b0);
                }
#pragma unroll
                for (int mt = 0; mt < 4; mt++)
#pragma unroll
                    for (int np = 0; np < 2; np++) {
                        MMA_F16(acc[mt][2 * np],     AH[mt], BH[np][0], BH[np][1]);
                        MMA_F16(acc[mt][2 * np + 1], AH[mt], BH[np][2], BH[np][3]);
                    }
            } else {
#pragma unroll
                for (int np = 0; np < 2; np++) {
                    uint32_t b0 = st + A_BYTES + (wc * 32 + np * 16 + lr) * 144 + kb;
                    LDSM4(BH[np], b0);
                }
#pragma unroll
                for (int mt = 0; mt < 4; mt++)
#pragma unroll
                    for (int np = 0; np < 2; np++) {
                        MMA_F16(acc[mt][2 * np],     AH[mt], BH[np][0], BH[np][2]);
                        MMA_F16(acc[mt][2 * np + 1], AH[mt], BH[np][1], BH[np][3]);
                    }
            }
        }
    }
#undef LOAD_STAGE

    const int rql = l >> 2, cpl = (l & 3) * 2;

    if (EXP) {
        // ---- QK epilogue: exp + causal mask + fp16 store + row partials ----
        __syncthreads();
        float* partS = reinterpret_cast<float*>(smem);   // [2][128]
#pragma unroll
        for (int mt = 0; mt < 4; mt++) {
            const int rl = wr * 64 + mt * 16 + rql;
            const int grow = by * 128 + rl;
            float p0 = 0.f, p1 = 0.f;
#pragma unroll
            for (int nt = 0; nt < 4; nt++) {
                const int col = bx * 64 + wc * 32 + nt * 8 + cpl;
                float e0 = (col     <= grow)     ? __expf(acc[mt][nt][0] * alpha) : 0.f;
                float e1 = (col + 1 <= grow)     ? __expf(acc[mt][nt][1] * alpha) : 0.f;
                float e2 = (col     <= grow + 8) ? __expf(acc[mt][nt][2] * alpha) : 0.f;
                float e3 = (col + 1 <= grow + 8) ? __expf(acc[mt][nt][3] * alpha) : 0.f;
                __half h0 = __float2half(e0), h1 = __float2half(e1);
                __half h2 = __float2half(e2), h3 = __float2half(e3);
                const long o0 = (long)bz * strideCz + (long)grow * ldc + col;
                *reinterpret_cast<uint32_t*>(Ch + o0) =
                    (uint32_t)__half_as_ushort(h0) | ((uint32_t)__half_as_ushort(h1) << 16);
                *reinterpret_cast<uint32_t*>(Ch + o0 + 8L * ldc) =
                    (uint32_t)__half_as_ushort(h2) | ((uint32_t)__half_as_ushort(h3) << 16);
                p0 += e0 + e1;
                p1 += e2 + e3;
            }
            p0 += __shfl_xor_sync(0xffffffffu, p0, 1);
            p0 += __shfl_xor_sync(0xffffffffu, p0, 2);
            p1 += __shfl_xor_sync(0xffffffffu, p1, 1);
            p1 += __shfl_xor_sync(0xffffffffu, p1, 2);
            if ((l & 3) == 0) {
                partS[wc * 128 + rl] = p0;
                partS[wc * 128 + rl + 8] = p1;
            }
        }
        __syncthreads();
        if (tid < 128) {
            float sv = partS[tid] + partS[128 + tid];
            part[((long)bz * SEQ + by * 128 + tid) * 32 + bx] = sv;
        }
        return;
    }

    // ---- standard epilogue ----
#pragma unroll
    for (int mt = 0; mt < 4; mt++) {
        const long row = (long)by * 128 + wr * 64 + mt * 16 + rql;
        float s0 = 1.f, s1 = 1.f;
        if (RSCALE) {
            s0 = invS[(long)bz * SEQ + row];
            s1 = invS[(long)bz * SEQ + row + 8];
        }
#pragma unroll
        for (int nt = 0; nt < 4; nt++) {
            const int col = bx * 64 + wc * 32 + nt * 8 + cpl;
            float v0 = acc[mt][nt][0] * alpha, v1 = acc[mt][nt][1] * alpha;
            float v2 = acc[mt][nt][2] * alpha, v3 = acc[mt][nt][3] * alpha;
            if (RSCALE) { v0 *= s0; v1 *= s0; v2 *= s1; v3 *= s1; }
            if (BIAS) {
                float b0 = bias[col], b1 = bias[col + 1];
                v0 += b0; v1 += b1; v2 += b0; v3 += b1;
            }
            const long o0 = (long)bz * strideCz + row * ldc + col;
            const long o1 = o0 + 8L * ldc;
            if (WF32) {
                *reinterpret_cast<float2*>(Cf + o0) = make_float2(v0, v1);
                *reinterpret_cast<float2*>(Cf + o1) = make_float2(v2, v3);
            } else {
                __half h0 = __float2half(v0), h1 = __float2half(v1);
                __half h2 = __float2half(v2), h3 = __float2half(v3);
                *reinterpret_cast<uint32_t*>(Ch + o0) =
                    (uint32_t)__half_as_ushort(h0) | ((uint32_t)__half_as_ushort(h1) << 16);
                *reinterpret_cast<uint32_t*>(Ch + o1) =
                    (uint32_t)__half_as_ushort(h2) | ((uint32_t)__half_as_ushort(h3) << 16);
            }
        }
    }
}

// ---------------------------------------------------------------------------
// fp32 -> fp16, 8 elems/thread (2x float4 in, 1x uint4 out).
// y-dim: 0..2 = xq/xk/xv (n elems), 3 = W (nW elems)
// ---------------------------------------------------------------------------
__global__ void __launch_bounds__(256) cvtH4(const float* __restrict__ i0,
                                             const float* __restrict__ i1,
                                             const float* __restrict__ i2,
                                             const float* __restrict__ i3,
                                             __half* __restrict__ o0,
                                             __half* __restrict__ o1,
                                             __half* __restrict__ o2,
                                             __half* __restrict__ o3,
                                             long n, long nW)
{
    const int y = blockIdx.y;
    const float* in = (y == 0) ? i0 : (y == 1) ? i1 : (y == 2) ? i2 : i3;
    __half* out = (y == 0) ? o0 : (y == 1) ? o1 : (y == 2) ? o2 : o3;
    const long lim = (y == 3) ? nW : n;
    long i = ((long)blockIdx.x * 256 + threadIdx.x) * 8;
    if (i >= lim) return;
    float4 a = *reinterpret_cast<const float4*>(in + i);
    float4 b = *reinterpret_cast<const float4*>(in + i + 4);
    __half h0 = __float2half(a.x), h1 = __float2half(a.y);
    __half h2 = __float2half(a.z), h3 = __float2half(a.w);
    __half h4 = __float2half(b.x), h5 = __float2half(b.y);
    __half h6 = __float2half(b.z), h7 = __float2half(b.w);
    uint4 v;
    v.x = (uint32_t)__half_as_ushort(h0) | ((uint32_t)__half_as_ushort(h1) << 16);
    v.y = (uint32_t)__half_as_ushort(h2) | ((uint32_t)__half_as_ushort(h3) << 16);
    v.z = (uint32_t)__half_as_ushort(h4) | ((uint32_t)__half_as_ushort(h5) << 16);
    v.w = (uint32_t)__half_as_ushort(h6) | ((uint32_t)__half_as_ushort(h7) << 16);
    *reinterpret_cast<uint4*>(out + i) = v;
}

// ---------------------------------------------------------------------------
// Warp-per-row invS reduction: lane i loads partial i (i < ntile), shfl-sum.
// ---------------------------------------------------------------------------
__global__ void __launch_bounds__(256) reduce_invS(const float* __restrict__ part,
                                                   float* __restrict__ invS)
{
    const int r = blockIdx.x * 8 + (threadIdx.x >> 5);
    const int lane = threadIdx.x & 31;
    const int q = r & (SEQ - 1);
    const int ntile = (q >> 6) + 1;
    float s = (lane < ntile) ? part[(long)r * 32 + lane] : 0.f;
#pragma unroll
    for (int o = 16; o > 0; o >>= 1) s += __shfl_xor_sync(0xffffffffu, s, o);
    if (lane == 0) invS[r] = 1.f / s;
}

// ---------------------------------------------------------------------------
extern "C" void kernel_launch(void* const* d_in, const int* in_sizes, int n_in,
                              void* d_out, int out_size)
{
    (void)in_sizes; (void)n_in; (void)out_size;
    const float* xq = (const float*)d_in[0];
    const float* xk = (const float*)d_in[1];
    const float* xv = (const float*)d_in[2];
    const float* Wq = (const float*)d_in[3];
    const float* bq = (const float*)d_in[4];
    float* out = (float*)d_out;

    void *x1, *W1, *QKV, *P1, *part, *invS;
    cudaGetSymbolAddress(&x1, g_x1);
    cudaGetSymbolAddress(&W1, g_W1);
    cudaGetSymbolAddress(&QKV, g_QKV);
    cudaGetSymbolAddress(&P1, g_P1);
    cudaGetSymbolAddress(&part, g_part);
    cudaGetSymbolAddress(&invS, g_invS);

    __half* X = (__half*)x1;
    __half* Q1 = (__half*)QKV;
    __half* K1 = Q1 + NELEM;
    __half* V1 = Q1 + 2 * NELEM;

    auto kProj = gemm_f16<false, false, true, false, false, false, false>;
    auto kQK   = gemm_f16<true,  false, false, false, false, true,  false>;
    auto kPV   = gemm_f16<false, true,  false, true,  true,  false, true>;
    cudaFuncSetAttribute(kProj, cudaFuncAttributeMaxDynamicSharedMemorySize, SMEM_REQ);
    cudaFuncSetAttribute(kQK,   cudaFuncAttributeMaxDynamicSharedMemorySize, SMEM_REQ);
    cudaFuncSetAttribute(kPV,   cudaFuncAttributeMaxDynamicSharedMemorySize, SMEM_REQ);

    // 1) fp32 -> fp16 conversions (x planes + W, one launch, 8 elems/thread)
    cvtH4<<<dim3((unsigned)(NELEM / 8 / 256), 4), 256>>>(
        xq, xk, xv, Wq, X, X + NELEM, X + 2 * NELEM, (__half*)W1,
        NELEM, (long)EMB * EMB);

    // 2) one launch: Q/K/V = x @ W^T + b -> fp16
    {
        dim3 g(EMB / 64, MTOT / 128, 3);
        kProj<<<g, 128, SMEM_REQ>>>(X, NELEM, (const __half*)W1, 0, EMB,
                                    EMB, 1.0f, bq, nullptr, nullptr,
                                    nullptr, Q1, EMB, NELEM);
    }

    // 3) QK + exp + mask + partial sums
    {
        dim3 g(SEQ / 64, SEQ / 128, BATCH);
        kQK<<<g, 128, SMEM_REQ>>>(Q1, (long)SEQ * EMB, K1, (long)SEQ * EMB, EMB,
                                  EMB, 0.03125f, nullptr, nullptr, (float*)part,
                                  nullptr, (__half*)P1, SEQ, (long)SEQ * SEQ);
    }

    // 4) invS = 1 / row-sum (warp per row)
    reduce_invS<<<MTOT / 8, 256>>>((const float*)part, (float*)invS);

    // 5) out = invS * (E @ V) — V consumed directly via ldmatrix.trans
    {
        dim3 g(EMB / 64, SEQ / 128, BATCH);
        kPV<<<g, 128, SMEM_REQ>>>((const __half*)P1, (long)SEQ * SEQ,
                                  V1, (long)SEQ * EMB, EMB,
                                  SEQ, 1.0f, nullptr, (const float*)invS, nullptr,
                                  out, nullptr, EMB, (long)SEQ * EMB);
    }
}